// round 9
// baseline (speedup 1.0000x reference)
#include <cuda_runtime.h>
#include <cuda_bf16.h>

#define N_NODES 50000
#define N_EDGES 800000
#define FEATS   128
#define TILE_R  64
#define WP_STRIDE 66    // u64 stride per W row (528 B): LDS.128 conflict-free
#define SCAN_BLK 1024
#define SCAN_GRID ((N_NODES + SCAN_BLK - 1) / SCAN_BLK)   // 49

#define GEMM_BLOCKS ((N_NODES + TILE_R - 1) / TILE_R)     // 782
#define EDGE_BLK_EDGES 1024                               // 256 thr * 4 edges
#define EDGE_BLOCKS ((N_EDGES + EDGE_BLK_EDGES - 1) / EDGE_BLK_EDGES) // 782

// ---------------- device scratch (alloc-free rule: __device__ globals) -----
__device__ float g_xf[(size_t)N_NODES * FEATS];   // feat @ W^T
__device__ int   g_cnt[N_NODES];                  // per-dst degree (re-zeroed by gather)
__device__ int   g_off[N_NODES + 1];              // CSR offsets
__device__ int   g_cur[N_NODES];                  // fill cursors
__device__ int   g_bucket[N_EDGES];               // src ids bucketed by dst
__device__ int   g_part[SCAN_GRID];               // per-block totals

#define FMA2(acc, a, w) asm("fma.rn.f32x2 %0, %1, %2, %0;" : "+l"(acc) : "l"(a), "l"(w))

// ---------------------------------------------------------------------------
// K1: histogram of dst. 4 edges/thread via int4.
// Requires g_cnt == 0 on entry (statics zero-init; gather re-zeroes each call).
// ---------------------------------------------------------------------------
__global__ void hist_kernel(const int* __restrict__ dst) {
    int e0 = blockIdx.x * EDGE_BLK_EDGES + threadIdx.x * 4;
    if (e0 + 3 < N_EDGES) {
        int4 d4 = *reinterpret_cast<const int4*>(dst + e0);
        if ((unsigned)d4.x < N_NODES) atomicAdd(&g_cnt[d4.x], 1);
        if ((unsigned)d4.y < N_NODES) atomicAdd(&g_cnt[d4.y], 1);
        if ((unsigned)d4.z < N_NODES) atomicAdd(&g_cnt[d4.z], 1);
        if ((unsigned)d4.w < N_NODES) atomicAdd(&g_cnt[d4.w], 1);
    } else {
        for (int e = e0; e < N_EDGES; e++) {
            int d = dst[e];
            if ((unsigned)d < N_NODES) atomicAdd(&g_cnt[d], 1);
        }
    }
}

// ---------------------------------------------------------------------------
// K2: per-block exclusive scan of g_cnt -> g_off; totals -> g_part.
// ---------------------------------------------------------------------------
__global__ void scan_local_kernel() {
    __shared__ int wsum[32];
    int tid  = threadIdx.x;
    int lane = tid & 31;
    int wid  = tid >> 5;
    int idx  = blockIdx.x * SCAN_BLK + tid;

    int x = (idx < N_NODES) ? g_cnt[idx] : 0;

    int v = x;
    #pragma unroll
    for (int d = 1; d < 32; d <<= 1) {
        int t = __shfl_up_sync(0xffffffff, v, d);
        if (lane >= d) v += t;
    }
    if (lane == 31) wsum[wid] = v;
    __syncthreads();
    if (wid == 0) {
        int w = wsum[lane];
        #pragma unroll
        for (int d = 1; d < 32; d <<= 1) {
            int t = __shfl_up_sync(0xffffffff, w, d);
            if (lane >= d) w += t;
        }
        wsum[lane] = w;
    }
    __syncthreads();

    int excl = v - x + ((wid > 0) ? wsum[wid - 1] : 0);
    if (idx < N_NODES) g_off[idx] = excl;
    if (tid == SCAN_BLK - 1) g_part[blockIdx.x] = excl + x;
}

// ---------------------------------------------------------------------------
// K3: add block offsets; copy to cursors; sentinel.
// ---------------------------------------------------------------------------
__global__ void scan_add_kernel() {
    __shared__ int s_off;
    int tid = threadIdx.x;
    if (tid < 32) {
        int v = 0;
        for (int j = tid; j < blockIdx.x; j += 32) v += g_part[j];
        #pragma unroll
        for (int d = 16; d > 0; d >>= 1) v += __shfl_down_sync(0xffffffff, v, d);
        if (tid == 0) s_off = v;
    }
    __syncthreads();

    int idx = blockIdx.x * SCAN_BLK + tid;
    if (idx < N_NODES) {
        int o = g_off[idx] + s_off;
        g_off[idx] = o;
        g_cur[idx] = o;
    }
    if (blockIdx.x == 0 && tid == 0) g_off[N_NODES] = N_EDGES;
}

// ---------------------------------------------------------------------------
// K4: FUSED fill + GEMM (independent work, one launch).
//   blocks [0, GEMM_BLOCKS)            : xf = feat @ W^T
//   blocks [GEMM_BLOCKS, +EDGE_BLOCKS) : bucket fill
// GEMM: warp = 8-row group; thread = 8 rows x 4 cols {lane+32j}.
//   W pre-packed f32x2 in smem (stride 66 u64) -> one LDS.128 per j per chunk,
//   A tile in smem, broadcast LDS.128 per row per chunk.
//   Per 4-k chunk per warp: 4 W LDS.128 + 8 A LDS.128 + 64 FFMA2 = 76 issues.
// ---------------------------------------------------------------------------
__global__ void __launch_bounds__(256, 2)
fill_gemm_kernel(const int* __restrict__ src,
                 const int* __restrict__ dst,
                 const float* __restrict__ A,   // feat [N,128]
                 const float* __restrict__ W)   // [128,128] row-major
{
    if (blockIdx.x < GEMM_BLOCKS) {
        // ---------------- GEMM role ----------------
        extern __shared__ unsigned long long smu[];
        unsigned long long* Wp = smu;                       // [128][66] u64
        float* As = reinterpret_cast<float*>(smu + FEATS * WP_STRIDE); // [64][128]

        const int tid  = threadIdx.x;
        const int lane = tid & 31;
        const int wid  = tid >> 5;              // 0..7: 8-row group
        const int row0 = blockIdx.x * TILE_R + wid * 8;

        // Stage W packed: read float2 (coalesced LDG.64), store u64.
        {
            const double* W2 = reinterpret_cast<const double*>(W); // reinterp only
            for (int i = tid; i < FEATS * 64; i += 256) {
                int c  = i >> 6;
                int k2 = i & 63;
                double v = W2[i];
                Wp[c * WP_STRIDE + k2] = *reinterpret_cast<unsigned long long*>(&v);
            }
        }
        // Stage A tile: coalesced float4, zero-pad past N_NODES.
        {
            const float4* A4 = reinterpret_cast<const float4*>(A);
            float4* As4 = reinterpret_cast<float4*>(As);
            int rbase = blockIdx.x * TILE_R;
            #pragma unroll
            for (int t = 0; t < 8; t++) {
                int i = tid + t * 256;          // 0..2047
                int r  = i >> 5;
                int c4 = i & 31;
                int row = rbase + r;
                As4[i] = (row < N_NODES) ? A4[(size_t)row * 32 + c4]
                                         : make_float4(0.f, 0.f, 0.f, 0.f);
            }
        }
        __syncthreads();

        unsigned long long acc[4][8];
        #pragma unroll
        for (int j = 0; j < 4; j++)
            #pragma unroll
            for (int r = 0; r < 8; r++) acc[j][r] = 0ull;

        // Per-thread W row bases (u64 units)
        int wbase[4];
        #pragma unroll
        for (int j = 0; j < 4; j++) wbase[j] = (lane + 32 * j) * WP_STRIDE;

        #pragma unroll 4
        for (int k = 0; k < FEATS; k += 4) {
            const int k2 = k >> 1;              // even -> 16B-aligned
            ulonglong2 wv[4];
            #pragma unroll
            for (int j = 0; j < 4; j++)
                wv[j] = *reinterpret_cast<const ulonglong2*>(&Wp[wbase[j] + k2]);
            #pragma unroll
            for (int r = 0; r < 8; r++) {
                // broadcast LDS.128 — same address across warp
                ulonglong2 a = *reinterpret_cast<const ulonglong2*>(
                    &As[(wid * 8 + r) * FEATS + k]);
                #pragma unroll
                for (int j = 0; j < 4; j++) {
                    FMA2(acc[j][r], a.x, wv[j].x);
                    FMA2(acc[j][r], a.y, wv[j].y);
                }
            }
        }

        #pragma unroll
        for (int r = 0; r < 8; r++) {
            int row = row0 + r;
            if (row < N_NODES) {
                #pragma unroll
                for (int j = 0; j < 4; j++) {
                    float2 f = *reinterpret_cast<float2*>(&acc[j][r]);
                    g_xf[(size_t)row * FEATS + lane + 32 * j] = f.x + f.y;
                }
            }
        }
    } else {
        // ---------------- fill role ----------------
        int b = blockIdx.x - GEMM_BLOCKS;
        int e0 = b * EDGE_BLK_EDGES + threadIdx.x * 4;
        if (e0 + 3 < N_EDGES) {
            int4 s4 = *reinterpret_cast<const int4*>(src + e0);
            int4 d4 = *reinterpret_cast<const int4*>(dst + e0);
            int p0 = ((unsigned)d4.x < N_NODES) ? atomicAdd(&g_cur[d4.x], 1) : -1;
            int p1 = ((unsigned)d4.y < N_NODES) ? atomicAdd(&g_cur[d4.y], 1) : -1;
            int p2 = ((unsigned)d4.z < N_NODES) ? atomicAdd(&g_cur[d4.z], 1) : -1;
            int p3 = ((unsigned)d4.w < N_NODES) ? atomicAdd(&g_cur[d4.w], 1) : -1;
            if (p0 >= 0 && (unsigned)s4.x < N_NODES) g_bucket[p0] = s4.x;
            if (p1 >= 0 && (unsigned)s4.y < N_NODES) g_bucket[p1] = s4.y;
            if (p2 >= 0 && (unsigned)s4.z < N_NODES) g_bucket[p2] = s4.z;
            if (p3 >= 0 && (unsigned)s4.w < N_NODES) g_bucket[p3] = s4.w;
        } else {
            for (int e = e0; e < N_EDGES; e++) {
                int d = dst[e];
                int s = src[e];
                if ((unsigned)d < N_NODES && (unsigned)s < N_NODES) {
                    int pos = atomicAdd(&g_cur[d], 1);
                    g_bucket[pos] = s;
                }
            }
        }
    }
}

// ---------------------------------------------------------------------------
// K5: out[d] = relu( sum_{s in nbrs(d)} xf[s] + bias ). Warp per node.
// Re-zeroes g_cnt for the next replay (state identical at call boundaries).
// ---------------------------------------------------------------------------
__global__ void gather_bias_relu_kernel(const float* __restrict__ bias,
                                        float* __restrict__ out) {
    int gtid = blockIdx.x * blockDim.x + threadIdx.x;
    if (gtid < N_NODES) g_cnt[gtid] = 0;

    int node = gtid >> 5;
    int lane = threadIdx.x & 31;
    if (node >= N_NODES) return;

    int beg = g_off[node];
    int end = g_off[node + 1];

    float4 acc = reinterpret_cast<const float4*>(bias)[lane];
    const float4* xf4 = reinterpret_cast<const float4*>(g_xf);

    int i = beg;
    for (; i + 4 <= end; i += 4) {
        int s0 = g_bucket[i + 0];
        int s1 = g_bucket[i + 1];
        int s2 = g_bucket[i + 2];
        int s3 = g_bucket[i + 3];
        float4 v0 = xf4[(size_t)s0 * 32 + lane];
        float4 v1 = xf4[(size_t)s1 * 32 + lane];
        float4 v2 = xf4[(size_t)s2 * 32 + lane];
        float4 v3 = xf4[(size_t)s3 * 32 + lane];
        acc.x += (v0.x + v1.x) + (v2.x + v3.x);
        acc.y += (v0.y + v1.y) + (v2.y + v3.y);
        acc.z += (v0.z + v1.z) + (v2.z + v3.z);
        acc.w += (v0.w + v1.w) + (v2.w + v3.w);
    }
    for (; i < end; i++) {
        int s = g_bucket[i];
        float4 v = xf4[(size_t)s * 32 + lane];
        acc.x += v.x; acc.y += v.y; acc.z += v.z; acc.w += v.w;
    }

    float4 r;
    r.x = fmaxf(acc.x, 0.f);
    r.y = fmaxf(acc.y, 0.f);
    r.z = fmaxf(acc.z, 0.f);
    r.w = fmaxf(acc.w, 0.f);
    reinterpret_cast<float4*>(out)[(size_t)node * 32 + lane] = r;
}

// ---------------------------------------------------------------------------
extern "C" void kernel_launch(void* const* d_in, const int* in_sizes, int n_in,
                              void* d_out, int out_size) {
    const float* feat = (const float*)d_in[0];   // [50000,128] f32
    const int*   src  = (const int*)d_in[1];     // [800000] i32
    const int*   dst  = (const int*)d_in[2];     // [800000] i32
    const float* W    = (const float*)d_in[3];   // [128,128] f32
    const float* bias = (const float*)d_in[4];   // [128] f32
    float*       out  = (float*)d_out;           // [50000,128] f32

    (void)in_sizes; (void)n_in; (void)out_size;

    // W packed (128*66*8 B) + A tile (64*128*4 B) = 67,584 + 32,768 = 100,352 B
    const int smem_bytes = FEATS * WP_STRIDE * 8 + TILE_R * FEATS * 4;
    cudaFuncSetAttribute(fill_gemm_kernel,
                         cudaFuncAttributeMaxDynamicSharedMemorySize, smem_bytes);

    hist_kernel<<<EDGE_BLOCKS, 256>>>(dst);
    scan_local_kernel<<<SCAN_GRID, SCAN_BLK>>>();
    scan_add_kernel<<<SCAN_GRID, SCAN_BLK>>>();
    fill_gemm_kernel<<<GEMM_BLOCKS + EDGE_BLOCKS, 256, smem_bytes>>>(src, dst, feat, W);

    {
        long long threads = (long long)N_NODES * 32;
        int blocks = (int)((threads + 255) / 256);
        gather_bias_relu_kernel<<<blocks, 256>>>(bias, out);
    }
}

// round 11
// speedup vs baseline: 1.2499x; 1.2499x over previous
#include <cuda_runtime.h>
#include <cuda_bf16.h>
#include <cstdint>

#define N_NODES 50000
#define N_EDGES 800000
#define FEATS   128
#define TILE_M  64
#define SCAN_BLK 1024
#define SCAN_GRID ((N_NODES + SCAN_BLK - 1) / SCAN_BLK)   // 49

#define GEMM_BLOCKS ((N_NODES + TILE_M - 1) / TILE_M)     // 782
#define EDGE_BLK_EDGES 1024                               // 256 thr * 4 edges
#define EDGE_BLOCKS ((N_EDGES + EDGE_BLK_EDGES - 1) / EDGE_BLK_EDGES) // 782
#define WPREP_BLOCKS 8

// smem tile geometry: bf16, row stride 136 elems = 272 B (ldmatrix conflict-free)
#define TSTRIDE_B 272
#define A_TILE_B  (TILE_M * TSTRIDE_B)    // 17,408
#define W_TILE_B  (FEATS * TSTRIDE_B)     // 34,816
#define SOFF_AHI  0
#define SOFF_ALO  (A_TILE_B)
#define SOFF_WHI  (2 * A_TILE_B)
#define SOFF_WLO  (2 * A_TILE_B + W_TILE_B)
#define SMEM_TOTAL (2 * A_TILE_B + 2 * W_TILE_B)          // 104,448

// ---------------- device scratch (alloc-free rule: __device__ globals) -----
__device__ float g_xf[(size_t)N_NODES * FEATS];   // feat @ W^T
__device__ int   g_cnt[N_NODES];                  // per-dst degree (re-zeroed by gather)
__device__ int   g_off[N_NODES + 1];              // CSR offsets
__device__ int   g_cur[N_NODES];                  // fill cursors
__device__ int   g_bucket[N_EDGES];               // src ids bucketed by dst
__device__ int   g_part[SCAN_GRID];               // per-block totals
__device__ uint4 g_whi[FEATS * 16];               // W hi bf16, [128][128] packed
__device__ uint4 g_wlo[FEATS * 16];               // W lo bf16

// ============================ helpers ======================================
__device__ __forceinline__ uint32_t smem_u32(const void* p) {
    uint32_t a;
    asm("{ .reg .u64 t; cvta.to.shared.u64 t, %1; cvt.u32.u64 %0, t; }"
        : "=r"(a) : "l"(p));
    return a;
}
__device__ __forceinline__ uint32_t cvt_bf16x2(float hi, float lo) {
    uint32_t r;
    asm("cvt.rn.bf16x2.f32 %0, %1, %2;" : "=r"(r) : "f"(hi), "f"(lo));
    return r;
}
// 8 consecutive floats -> hi uint4 + lo uint4 (bf16 element order preserved)
__device__ __forceinline__ void split8(const float4 u, const float4 v,
                                       uint4& hi, uint4& lo) {
    hi.x = cvt_bf16x2(u.y, u.x);
    hi.y = cvt_bf16x2(u.w, u.z);
    hi.z = cvt_bf16x2(v.y, v.x);
    hi.w = cvt_bf16x2(v.w, v.z);
    float h0 = __uint_as_float(hi.x << 16), h1 = __uint_as_float(hi.x & 0xFFFF0000u);
    float h2 = __uint_as_float(hi.y << 16), h3 = __uint_as_float(hi.y & 0xFFFF0000u);
    float h4 = __uint_as_float(hi.z << 16), h5 = __uint_as_float(hi.z & 0xFFFF0000u);
    float h6 = __uint_as_float(hi.w << 16), h7 = __uint_as_float(hi.w & 0xFFFF0000u);
    lo.x = cvt_bf16x2(u.y - h1, u.x - h0);
    lo.y = cvt_bf16x2(u.w - h3, u.z - h2);
    lo.z = cvt_bf16x2(v.y - h5, v.x - h4);
    lo.w = cvt_bf16x2(v.w - h7, v.z - h6);
}
#define LDSM_X4(r0, r1, r2, r3, addr)                                         \
    asm volatile("ldmatrix.sync.aligned.m8n8.x4.shared.b16 {%0,%1,%2,%3}, [%4];" \
                 : "=r"(r0), "=r"(r1), "=r"(r2), "=r"(r3) : "r"(addr))
#define MMA_BF16(d, a, b0, b1)                                                \
    asm volatile("mma.sync.aligned.m16n8k16.row.col.f32.bf16.bf16.f32 "       \
                 "{%0,%1,%2,%3}, {%4,%5,%6,%7}, {%8,%9}, {%0,%1,%2,%3};"      \
                 : "+f"(d[0]), "+f"(d[1]), "+f"(d[2]), "+f"(d[3])             \
                 : "r"(a[0]), "r"(a[1]), "r"(a[2]), "r"(a[3]), "r"(b0), "r"(b1))

// ---------------------------------------------------------------------------
// K1: histogram of dst (blocks < EDGE_BLOCKS) + W hi/lo split (8 extra blocks).
// Requires g_cnt == 0 on entry (statics zero-init; gather re-zeroes each call).
// ---------------------------------------------------------------------------
__global__ void hist_kernel(const int* __restrict__ dst,
                            const float* __restrict__ W) {
    if (blockIdx.x < EDGE_BLOCKS) {
        int e0 = blockIdx.x * EDGE_BLK_EDGES + threadIdx.x * 4;
        if (e0 + 3 < N_EDGES) {
            int4 d4 = *reinterpret_cast<const int4*>(dst + e0);
            if ((unsigned)d4.x < N_NODES) atomicAdd(&g_cnt[d4.x], 1);
            if ((unsigned)d4.y < N_NODES) atomicAdd(&g_cnt[d4.y], 1);
            if ((unsigned)d4.z < N_NODES) atomicAdd(&g_cnt[d4.z], 1);
            if ((unsigned)d4.w < N_NODES) atomicAdd(&g_cnt[d4.w], 1);
        } else {
            for (int e = e0; e < N_EDGES; e++) {
                int d = dst[e];
                if ((unsigned)d < N_NODES) atomicAdd(&g_cnt[d], 1);
            }
        }
    } else {
        // W-prep: split W into bf16 hi/lo, 2048 threads x 8 floats
        int g = (blockIdx.x - EDGE_BLOCKS) * 256 + threadIdx.x;  // 0..2047
        int row = g >> 4, ch = g & 15;
        const float4* W4 = reinterpret_cast<const float4*>(W);
        float4 u = W4[row * 32 + ch * 2];
        float4 v = W4[row * 32 + ch * 2 + 1];
        uint4 hi, lo;
        split8(u, v, hi, lo);
        g_whi[row * 16 + ch] = hi;
        g_wlo[row * 16 + ch] = lo;
    }
}

// ---------------------------------------------------------------------------
// K2: per-block exclusive scan of g_cnt -> g_off; totals -> g_part.
// ---------------------------------------------------------------------------
__global__ void scan_local_kernel() {
    __shared__ int wsum[32];
    int tid  = threadIdx.x;
    int lane = tid & 31;
    int wid  = tid >> 5;
    int idx  = blockIdx.x * SCAN_BLK + tid;

    int x = (idx < N_NODES) ? g_cnt[idx] : 0;

    int v = x;
    #pragma unroll
    for (int d = 1; d < 32; d <<= 1) {
        int t = __shfl_up_sync(0xffffffff, v, d);
        if (lane >= d) v += t;
    }
    if (lane == 31) wsum[wid] = v;
    __syncthreads();
    if (wid == 0) {
        int w = wsum[lane];
        #pragma unroll
        for (int d = 1; d < 32; d <<= 1) {
            int t = __shfl_up_sync(0xffffffff, w, d);
            if (lane >= d) w += t;
        }
        wsum[lane] = w;
    }
    __syncthreads();

    int excl = v - x + ((wid > 0) ? wsum[wid - 1] : 0);
    if (idx < N_NODES) g_off[idx] = excl;
    if (tid == SCAN_BLK - 1) g_part[blockIdx.x] = excl + x;
}

// ---------------------------------------------------------------------------
// K3: add block offsets; copy to cursors; sentinel.
// ---------------------------------------------------------------------------
__global__ void scan_add_kernel() {
    __shared__ int s_off;
    int tid = threadIdx.x;
    if (tid < 32) {
        int v = 0;
        for (int j = tid; j < blockIdx.x; j += 32) v += g_part[j];
        #pragma unroll
        for (int d = 16; d > 0; d >>= 1) v += __shfl_down_sync(0xffffffff, v, d);
        if (tid == 0) s_off = v;
    }
    __syncthreads();

    int idx = blockIdx.x * SCAN_BLK + tid;
    if (idx < N_NODES) {
        int o = g_off[idx] + s_off;
        g_off[idx] = o;
        g_cur[idx] = o;
    }
    if (blockIdx.x == 0 && tid == 0) g_off[N_NODES] = N_EDGES;
}

// ---------------------------------------------------------------------------
// K4: FUSED fill + HMMA GEMM.
//   blocks [0, GEMM_BLOCKS)            : xf = feat @ W^T (mma.sync bf16 split)
//   blocks [GEMM_BLOCKS, +EDGE_BLOCKS) : bucket fill
// GEMM: 64-row tile; 8 warps = 4 m-tiles x 2 col-halves (64 cols each).
// Chains: Ahi*Whi + Ahi*Wlo + Alo*Whi, fp32 acc (error ~2^-17).
// ---------------------------------------------------------------------------
__global__ void __launch_bounds__(256)
fill_gemm_kernel(const int* __restrict__ src,
                 const int* __restrict__ dst,
                 const float* __restrict__ A)   // feat [N,128]
{
    if (blockIdx.x < GEMM_BLOCKS) {
        // ---------------- GEMM role ----------------
        extern __shared__ char smc[];
        const uint32_t sb = smem_u32(smc);
        const int tid  = threadIdx.x;
        const int lane = tid & 31;
        const int wid  = tid >> 5;
        const int row0 = blockIdx.x * TILE_M;

        // ---- stage A hi/lo: 64 rows x 16 chunks of 8 floats ----
        {
            const float4* A4 = reinterpret_cast<const float4*>(A);
            #pragma unroll
            for (int t = 0; t < 4; t++) {
                int i = tid + t * 256;          // 0..1023
                int r = i >> 4, g = i & 15;
                int row = row0 + r;
                float4 u, v;
                if (row < N_NODES) {
                    u = A4[(size_t)row * 32 + g * 2];
                    v = A4[(size_t)row * 32 + g * 2 + 1];
                } else {
                    u = make_float4(0.f, 0.f, 0.f, 0.f);
                    v = u;
                }
                uint4 hi, lo;
                split8(u, v, hi, lo);
                int off = r * TSTRIDE_B + g * 16;
                *reinterpret_cast<uint4*>(smc + SOFF_AHI + off) = hi;
                *reinterpret_cast<uint4*>(smc + SOFF_ALO + off) = lo;
            }
        }
        // ---- stage W hi/lo from pre-split globals ----
        {
            #pragma unroll
            for (int t = 0; t < 8; t++) {
                int i = tid + t * 256;          // 0..2047
                int r = i >> 4, g = i & 15;
                int off = r * TSTRIDE_B + g * 16;
                *reinterpret_cast<uint4*>(smc + SOFF_WHI + off) = g_whi[i];
                *reinterpret_cast<uint4*>(smc + SOFF_WLO + off) = g_wlo[i];
            }
        }
        __syncthreads();

        const int mt = wid & 3;                 // m-tile (16 rows)
        const int ch = wid >> 2;                // col half (64 cols)

        // ldmatrix base addresses (k advances by 32 B per step)
        // A: lanes 0-15 -> row mt*16 + lane, col k; lanes 16-31 -> same rows, k+8
        uint32_t a_addr = sb + ((lane & 15) + mt * 16) * TSTRIDE_B
                        + (lane >> 4) * 16;
        // W: quad q = lane>>3, lr = lane&7:
        //   row = n0 + lr + (q>>1)*8 ; col = k + (q&1)*8
        const int lr = lane & 7, q = lane >> 3;
        uint32_t w_row_part = (uint32_t)(lr + ((q >> 1) << 3)) * TSTRIDE_B
                            + (uint32_t)((q & 1) << 4);

        float acc[8][4];
        #pragma unroll
        for (int nt = 0; nt < 8; nt++)
            #pragma unroll
            for (int c = 0; c < 4; c++) acc[nt][c] = 0.f;

        #pragma unroll 2
        for (int ks = 0; ks < 8; ks++) {
            const uint32_t kb = ks * 32;        // byte offset of k-step
            uint32_t ahi[4], alo[4];
            LDSM_X4(ahi[0], ahi[1], ahi[2], ahi[3], a_addr + SOFF_AHI + kb);
            LDSM_X4(alo[0], alo[1], alo[2], alo[3], a_addr + SOFF_ALO + kb);

            #pragma unroll
            for (int np = 0; np < 4; np++) {    // n-pair: n-tiles 2np, 2np+1
                uint32_t wbase = sb + (uint32_t)(ch * 64 + np * 16) * TSTRIDE_B
                               + w_row_part + kb;
                uint32_t bh[4], bl[4];
                LDSM_X4(bh[0], bh[1], bh[2], bh[3], wbase + SOFF_WHI);
                LDSM_X4(bl[0], bl[1], bl[2], bl[3], wbase + SOFF_WLO);
                MMA_BF16(acc[2 * np],     ahi, bh[0], bh[1]);
                MMA_BF16(acc[2 * np],     ahi, bl[0], bl[1]);
                MMA_BF16(acc[2 * np],     alo, bh[0], bh[1]);
                MMA_BF16(acc[2 * np + 1], ahi, bh[2], bh[3]);
                MMA_BF16(acc[2 * np + 1], ahi, bl[2], bl[3]);
                MMA_BF16(acc[2 * np + 1], alo, bh[2], bh[3]);
            }
        }

        // ---- epilogue: lane l holds C[l/4][2(l%4)+{0,1}] and row +8 ----
        {
            int r0 = row0 + mt * 16 + (lane >> 2);
            int c0 = ch * 64 + 2 * (lane & 3);
            #pragma unroll
            for (int nt = 0; nt < 8; nt++) {
                int col = c0 + nt * 8;
                if (r0 < N_NODES)
                    *reinterpret_cast<float2*>(&g_xf[(size_t)r0 * FEATS + col]) =
                        make_float2(acc[nt][0], acc[nt][1]);
                if (r0 + 8 < N_NODES)
                    *reinterpret_cast<float2*>(&g_xf[(size_t)(r0 + 8) * FEATS + col]) =
                        make_float2(acc[nt][2], acc[nt][3]);
            }
        }
    } else {
        // ---------------- fill role ----------------
        int b = blockIdx.x - GEMM_BLOCKS;
        int e0 = b * EDGE_BLK_EDGES + threadIdx.x * 4;
        if (e0 + 3 < N_EDGES) {
            int4 s4 = *reinterpret_cast<const int4*>(src + e0);
            int4 d4 = *reinterpret_cast<const int4*>(dst + e0);
            int p0 = ((unsigned)d4.x < N_NODES) ? atomicAdd(&g_cur[d4.x], 1) : -1;
            int p1 = ((unsigned)d4.y < N_NODES) ? atomicAdd(&g_cur[d4.y], 1) : -1;
            int p2 = ((unsigned)d4.z < N_NODES) ? atomicAdd(&g_cur[d4.z], 1) : -1;
            int p3 = ((unsigned)d4.w < N_NODES) ? atomicAdd(&g_cur[d4.w], 1) : -1;
            if (p0 >= 0 && (unsigned)s4.x < N_NODES) g_bucket[p0] = s4.x;
            if (p1 >= 0 && (unsigned)s4.y < N_NODES) g_bucket[p1] = s4.y;
            if (p2 >= 0 && (unsigned)s4.z < N_NODES) g_bucket[p2] = s4.z;
            if (p3 >= 0 && (unsigned)s4.w < N_NODES) g_bucket[p3] = s4.w;
        } else {
            for (int e = e0; e < N_EDGES; e++) {
                int d = dst[e];
                int s = src[e];
                if ((unsigned)d < N_NODES && (unsigned)s < N_NODES) {
                    int pos = atomicAdd(&g_cur[d], 1);
                    g_bucket[pos] = s;
                }
            }
        }
    }
}

// ---------------------------------------------------------------------------
// K5: out[d] = relu( sum_{s in nbrs(d)} xf[s] + bias ). Warp per node.
// Re-zeroes g_cnt for the next replay.
// ---------------------------------------------------------------------------
__global__ void gather_bias_relu_kernel(const float* __restrict__ bias,
                                        float* __restrict__ out) {
    int gtid = blockIdx.x * blockDim.x + threadIdx.x;
    if (gtid < N_NODES) g_cnt[gtid] = 0;

    int node = gtid >> 5;
    int lane = threadIdx.x & 31;
    if (node >= N_NODES) return;

    int beg = g_off[node];
    int end = g_off[node + 1];

    float4 acc = reinterpret_cast<const float4*>(bias)[lane];
    const float4* xf4 = reinterpret_cast<const float4*>(g_xf);

    int i = beg;
    for (; i + 4 <= end; i += 4) {
        int s0 = g_bucket[i + 0];
        int s1 = g_bucket[i + 1];
        int s2 = g_bucket[i + 2];
        int s3 = g_bucket[i + 3];
        float4 v0 = xf4[(size_t)s0 * 32 + lane];
        float4 v1 = xf4[(size_t)s1 * 32 + lane];
        float4 v2 = xf4[(size_t)s2 * 32 + lane];
        float4 v3 = xf4[(size_t)s3 * 32 + lane];
        acc.x += (v0.x + v1.x) + (v2.x + v3.x);
        acc.y += (v0.y + v1.y) + (v2.y + v3.y);
        acc.z += (v0.z + v1.z) + (v2.z + v3.z);
        acc.w += (v0.w + v1.w) + (v2.w + v3.w);
    }
    for (; i < end; i++) {
        int s = g_bucket[i];
        float4 v = xf4[(size_t)s * 32 + lane];
        acc.x += v.x; acc.y += v.y; acc.z += v.z; acc.w += v.w;
    }

    float4 r;
    r.x = fmaxf(acc.x, 0.f);
    r.y = fmaxf(acc.y, 0.f);
    r.z = fmaxf(acc.z, 0.f);
    r.w = fmaxf(acc.w, 0.f);
    reinterpret_cast<float4*>(out)[(size_t)node * 32 + lane] = r;
}

// ---------------------------------------------------------------------------
extern "C" void kernel_launch(void* const* d_in, const int* in_sizes, int n_in,
                              void* d_out, int out_size) {
    const float* feat = (const float*)d_in[0];   // [50000,128] f32
    const int*   src  = (const int*)d_in[1];     // [800000] i32
    const int*   dst  = (const int*)d_in[2];     // [800000] i32
    const float* W    = (const float*)d_in[3];   // [128,128] f32
    const float* bias = (const float*)d_in[4];   // [128] f32
    float*       out  = (float*)d_out;           // [50000,128] f32

    (void)in_sizes; (void)n_in; (void)out_size;

    cudaFuncSetAttribute(fill_gemm_kernel,
                         cudaFuncAttributeMaxDynamicSharedMemorySize, SMEM_TOTAL);

    hist_kernel<<<EDGE_BLOCKS + WPREP_BLOCKS, 256>>>(dst, W);
    scan_local_kernel<<<SCAN_GRID, SCAN_BLK>>>();
    scan_add_kernel<<<SCAN_GRID, SCAN_BLK>>>();
    fill_gemm_kernel<<<GEMM_BLOCKS + EDGE_BLOCKS, 256, SMEM_TOTAL>>>(src, dst, feat);

    {
        long long threads = (long long)N_NODES * 32;
        int blocks = (int)((threads + 255) / 256);
        gather_bias_relu_kernel<<<blocks, 256>>>(bias, out);
    }
}

// round 12
// speedup vs baseline: 1.3518x; 1.0815x over previous
#include <cuda_runtime.h>
#include <cuda_bf16.h>
#include <cstdint>

#define N_NODES 50000
#define N_EDGES 800000
#define FEATS   128
#define TILE_M  128
#define SCAN_BLK 1024
#define SCAN_GRID ((N_NODES + SCAN_BLK - 1) / SCAN_BLK)   // 49

#define GEMM_BLOCKS ((N_NODES + TILE_M - 1) / TILE_M)     // 391
#define HIST_BLK_EDGES 1024
#define HIST_BLOCKS ((N_EDGES + HIST_BLK_EDGES - 1) / HIST_BLK_EDGES) // 782
#define EDGE_BLK_EDGES 2048                               // 512 thr * 4 edges
#define EDGE_BLOCKS ((N_EDGES + EDGE_BLK_EDGES - 1) / EDGE_BLK_EDGES) // 391
#define WPREP_BLOCKS 8

// smem tile geometry: bf16, row stride 136 elems = 272 B (ldmatrix conflict-free)
#define TSTRIDE_B 272
#define A_TILE_B  (TILE_M * TSTRIDE_B)    // 34,816
#define W_TILE_B  (FEATS * TSTRIDE_B)     // 34,816
#define SOFF_AHI  0
#define SOFF_ALO  (A_TILE_B)
#define SOFF_WHI  (2 * A_TILE_B)
#define SOFF_WLO  (2 * A_TILE_B + W_TILE_B)
#define SMEM_TOTAL (2 * A_TILE_B + 2 * W_TILE_B)          // 139,264

// ---------------- device scratch (alloc-free rule: __device__ globals) -----
__device__ float g_xf[(size_t)N_NODES * FEATS];   // feat @ W^T
__device__ int   g_cnt[N_NODES];                  // per-dst degree (re-zeroed by gather)
__device__ int   g_off[N_NODES + 1];              // CSR offsets
__device__ int   g_cur[N_NODES];                  // fill cursors
__device__ int   g_bucket[N_EDGES];               // src ids bucketed by dst
__device__ int   g_part[SCAN_GRID];               // per-block totals
__device__ uint4 g_whi[FEATS * 16];               // W hi bf16, [128][128] packed
__device__ uint4 g_wlo[FEATS * 16];               // W lo bf16

// ============================ helpers ======================================
__device__ __forceinline__ uint32_t smem_u32(const void* p) {
    uint32_t a;
    asm("{ .reg .u64 t; cvta.to.shared.u64 t, %1; cvt.u32.u64 %0, t; }"
        : "=r"(a) : "l"(p));
    return a;
}
__device__ __forceinline__ uint32_t cvt_bf16x2(float hi, float lo) {
    uint32_t r;
    asm("cvt.rn.bf16x2.f32 %0, %1, %2;" : "=r"(r) : "f"(hi), "f"(lo));
    return r;
}
__device__ __forceinline__ void split8(const float4 u, const float4 v,
                                       uint4& hi, uint4& lo) {
    hi.x = cvt_bf16x2(u.y, u.x);
    hi.y = cvt_bf16x2(u.w, u.z);
    hi.z = cvt_bf16x2(v.y, v.x);
    hi.w = cvt_bf16x2(v.w, v.z);
    float h0 = __uint_as_float(hi.x << 16), h1 = __uint_as_float(hi.x & 0xFFFF0000u);
    float h2 = __uint_as_float(hi.y << 16), h3 = __uint_as_float(hi.y & 0xFFFF0000u);
    float h4 = __uint_as_float(hi.z << 16), h5 = __uint_as_float(hi.z & 0xFFFF0000u);
    float h6 = __uint_as_float(hi.w << 16), h7 = __uint_as_float(hi.w & 0xFFFF0000u);
    lo.x = cvt_bf16x2(u.y - h1, u.x - h0);
    lo.y = cvt_bf16x2(u.w - h3, u.z - h2);
    lo.z = cvt_bf16x2(v.y - h5, v.x - h4);
    lo.w = cvt_bf16x2(v.w - h7, v.z - h6);
}
#define LDSM_X4(r0, r1, r2, r3, addr)                                         \
    asm volatile("ldmatrix.sync.aligned.m8n8.x4.shared.b16 {%0,%1,%2,%3}, [%4];" \
                 : "=r"(r0), "=r"(r1), "=r"(r2), "=r"(r3) : "r"(addr))
#define MMA_BF16(d, a, b0, b1)                                                \
    asm volatile("mma.sync.aligned.m16n8k16.row.col.f32.bf16.bf16.f32 "       \
                 "{%0,%1,%2,%3}, {%4,%5,%6,%7}, {%8,%9}, {%0,%1,%2,%3};"      \
                 : "+f"(d[0]), "+f"(d[1]), "+f"(d[2]), "+f"(d[3])             \
                 : "r"(a[0]), "r"(a[1]), "r"(a[2]), "r"(a[3]), "r"(b0), "r"(b1))

// ---------------------------------------------------------------------------
// K1: histogram of dst (256 thr) + W hi/lo split (8 extra blocks).
// ---------------------------------------------------------------------------
__global__ void hist_kernel(const int* __restrict__ dst,
                            const float* __restrict__ W) {
    if (blockIdx.x < HIST_BLOCKS) {
        int e0 = blockIdx.x * HIST_BLK_EDGES + threadIdx.x * 4;
        if (e0 + 3 < N_EDGES) {
            int4 d4 = *reinterpret_cast<const int4*>(dst + e0);
            if ((unsigned)d4.x < N_NODES) atomicAdd(&g_cnt[d4.x], 1);
            if ((unsigned)d4.y < N_NODES) atomicAdd(&g_cnt[d4.y], 1);
            if ((unsigned)d4.z < N_NODES) atomicAdd(&g_cnt[d4.z], 1);
            if ((unsigned)d4.w < N_NODES) atomicAdd(&g_cnt[d4.w], 1);
        } else {
            for (int e = e0; e < N_EDGES; e++) {
                int d = dst[e];
                if ((unsigned)d < N_NODES) atomicAdd(&g_cnt[d], 1);
            }
        }
    } else {
        int g = (blockIdx.x - HIST_BLOCKS) * 256 + threadIdx.x;  // 0..2047
        int row = g >> 4, ch = g & 15;
        const float4* W4 = reinterpret_cast<const float4*>(W);
        float4 u = W4[row * 32 + ch * 2];
        float4 v = W4[row * 32 + ch * 2 + 1];
        uint4 hi, lo;
        split8(u, v, hi, lo);
        g_whi[row * 16 + ch] = hi;
        g_wlo[row * 16 + ch] = lo;
    }
}

// ---------------------------------------------------------------------------
// K2: per-block exclusive scan of g_cnt -> g_off; totals -> g_part.
// ---------------------------------------------------------------------------
__global__ void scan_local_kernel() {
    __shared__ int wsum[32];
    int tid  = threadIdx.x;
    int lane = tid & 31;
    int wid  = tid >> 5;
    int idx  = blockIdx.x * SCAN_BLK + tid;

    int x = (idx < N_NODES) ? g_cnt[idx] : 0;

    int v = x;
    #pragma unroll
    for (int d = 1; d < 32; d <<= 1) {
        int t = __shfl_up_sync(0xffffffff, v, d);
        if (lane >= d) v += t;
    }
    if (lane == 31) wsum[wid] = v;
    __syncthreads();
    if (wid == 0) {
        int w = wsum[lane];
        #pragma unroll
        for (int d = 1; d < 32; d <<= 1) {
            int t = __shfl_up_sync(0xffffffff, w, d);
            if (lane >= d) w += t;
        }
        wsum[lane] = w;
    }
    __syncthreads();

    int excl = v - x + ((wid > 0) ? wsum[wid - 1] : 0);
    if (idx < N_NODES) g_off[idx] = excl;
    if (tid == SCAN_BLK - 1) g_part[blockIdx.x] = excl + x;
}

// ---------------------------------------------------------------------------
// K3: add block offsets; copy to cursors; sentinel.
// ---------------------------------------------------------------------------
__global__ void scan_add_kernel() {
    __shared__ int s_off;
    int tid = threadIdx.x;
    if (tid < 32) {
        int v = 0;
        for (int j = tid; j < blockIdx.x; j += 32) v += g_part[j];
        #pragma unroll
        for (int d = 16; d > 0; d >>= 1) v += __shfl_down_sync(0xffffffff, v, d);
        if (tid == 0) s_off = v;
    }
    __syncthreads();

    int idx = blockIdx.x * SCAN_BLK + tid;
    if (idx < N_NODES) {
        int o = g_off[idx] + s_off;
        g_off[idx] = o;
        g_cur[idx] = o;
    }
    if (blockIdx.x == 0 && tid == 0) g_off[N_NODES] = N_EDGES;
}

// ---------------------------------------------------------------------------
// K4: FUSED fill + HMMA GEMM, 512 threads.
//   blocks [0, GEMM_BLOCKS)            : xf = feat @ W^T, 128-row tiles
//   blocks [GEMM_BLOCKS, +EDGE_BLOCKS) : bucket fill (2048 edges/block)
// GEMM: 16 warps = 8 m-tiles x 2 col-halves. Full k-unroll for pipelining.
// Chains: Ahi*Whi + Ahi*Wlo + Alo*Whi, fp32 acc.
// ---------------------------------------------------------------------------
__global__ void __launch_bounds__(512)
fill_gemm_kernel(const int* __restrict__ src,
                 const int* __restrict__ dst,
                 const float* __restrict__ A)   // feat [N,128]
{
    if (blockIdx.x < GEMM_BLOCKS) {
        // ---------------- GEMM role ----------------
        extern __shared__ char smc[];
        const uint32_t sb = smem_u32(smc);
        const int tid  = threadIdx.x;
        const int lane = tid & 31;
        const int wid  = tid >> 5;              // 0..15
        const int row0 = blockIdx.x * TILE_M;

        // ---- stage A hi/lo: 128 rows x 16 chunks of 8 floats ----
        {
            const float4* A4 = reinterpret_cast<const float4*>(A);
            #pragma unroll
            for (int t = 0; t < 4; t++) {
                int i = tid + t * 512;          // 0..2047
                int r = i >> 4, g = i & 15;
                int row = row0 + r;
                float4 u, v;
                if (row < N_NODES) {
                    u = A4[(size_t)row * 32 + g * 2];
                    v = A4[(size_t)row * 32 + g * 2 + 1];
                } else {
                    u = make_float4(0.f, 0.f, 0.f, 0.f);
                    v = u;
                }
                uint4 hi, lo;
                split8(u, v, hi, lo);
                int off = r * TSTRIDE_B + g * 16;
                *reinterpret_cast<uint4*>(smc + SOFF_AHI + off) = hi;
                *reinterpret_cast<uint4*>(smc + SOFF_ALO + off) = lo;
            }
        }
        // ---- stage W hi/lo from pre-split globals ----
        {
            #pragma unroll
            for (int t = 0; t < 4; t++) {
                int i = tid + t * 512;          // 0..2047
                int r = i >> 4, g = i & 15;
                int off = r * TSTRIDE_B + g * 16;
                *reinterpret_cast<uint4*>(smc + SOFF_WHI + off) = g_whi[i];
                *reinterpret_cast<uint4*>(smc + SOFF_WLO + off) = g_wlo[i];
            }
        }
        __syncthreads();

        const int mt = wid & 7;                 // m-tile (16 rows)
        const int ch = wid >> 3;                // col half (64 cols)

        // ldmatrix addresses
        uint32_t a_addr = sb + ((lane & 15) + mt * 16) * TSTRIDE_B
                        + (lane >> 4) * 16;
        const int lr = lane & 7, q = lane >> 3;
        uint32_t w_row_part = (uint32_t)(lr + ((q >> 1) << 3)) * TSTRIDE_B
                            + (uint32_t)((q & 1) << 4);

        float acc[8][4];
        #pragma unroll
        for (int nt = 0; nt < 8; nt++)
            #pragma unroll
            for (int c = 0; c < 4; c++) acc[nt][c] = 0.f;

        #pragma unroll
        for (int ks = 0; ks < 8; ks++) {
            const uint32_t kb = ks * 32;
            uint32_t ahi[4], alo[4];
            LDSM_X4(ahi[0], ahi[1], ahi[2], ahi[3], a_addr + SOFF_AHI + kb);
            LDSM_X4(alo[0], alo[1], alo[2], alo[3], a_addr + SOFF_ALO + kb);

            #pragma unroll
            for (int np = 0; np < 4; np++) {
                uint32_t wbase = sb + (uint32_t)(ch * 64 + np * 16) * TSTRIDE_B
                               + w_row_part + kb;
                uint32_t bh[4], bl[4];
                LDSM_X4(bh[0], bh[1], bh[2], bh[3], wbase + SOFF_WHI);
                LDSM_X4(bl[0], bl[1], bl[2], bl[3], wbase + SOFF_WLO);
                MMA_BF16(acc[2 * np],     ahi, bh[0], bh[1]);
                MMA_BF16(acc[2 * np],     ahi, bl[0], bl[1]);
                MMA_BF16(acc[2 * np],     alo, bh[0], bh[1]);
                MMA_BF16(acc[2 * np + 1], ahi, bh[2], bh[3]);
                MMA_BF16(acc[2 * np + 1], ahi, bl[2], bl[3]);
                MMA_BF16(acc[2 * np + 1], alo, bh[2], bh[3]);
            }
        }

        // ---- epilogue ----
        {
            int r0 = row0 + mt * 16 + (lane >> 2);
            int c0 = ch * 64 + 2 * (lane & 3);
            #pragma unroll
            for (int nt = 0; nt < 8; nt++) {
                int col = c0 + nt * 8;
                if (r0 < N_NODES)
                    *reinterpret_cast<float2*>(&g_xf[(size_t)r0 * FEATS + col]) =
                        make_float2(acc[nt][0], acc[nt][1]);
                if (r0 + 8 < N_NODES)
                    *reinterpret_cast<float2*>(&g_xf[(size_t)(r0 + 8) * FEATS + col]) =
                        make_float2(acc[nt][2], acc[nt][3]);
            }
        }
    } else {
        // ---------------- fill role ----------------
        int b = blockIdx.x - GEMM_BLOCKS;
        int e0 = b * EDGE_BLK_EDGES + threadIdx.x * 4;
        if (e0 + 3 < N_EDGES) {
            int4 s4 = *reinterpret_cast<const int4*>(src + e0);
            int4 d4 = *reinterpret_cast<const int4*>(dst + e0);
            int p0 = ((unsigned)d4.x < N_NODES) ? atomicAdd(&g_cur[d4.x], 1) : -1;
            int p1 = ((unsigned)d4.y < N_NODES) ? atomicAdd(&g_cur[d4.y], 1) : -1;
            int p2 = ((unsigned)d4.z < N_NODES) ? atomicAdd(&g_cur[d4.z], 1) : -1;
            int p3 = ((unsigned)d4.w < N_NODES) ? atomicAdd(&g_cur[d4.w], 1) : -1;
            if (p0 >= 0 && (unsigned)s4.x < N_NODES) g_bucket[p0] = s4.x;
            if (p1 >= 0 && (unsigned)s4.y < N_NODES) g_bucket[p1] = s4.y;
            if (p2 >= 0 && (unsigned)s4.z < N_NODES) g_bucket[p2] = s4.z;
            if (p3 >= 0 && (unsigned)s4.w < N_NODES) g_bucket[p3] = s4.w;
        } else {
            for (int e = e0; e < N_EDGES; e++) {
                int d = dst[e];
                int s = src[e];
                if ((unsigned)d < N_NODES && (unsigned)s < N_NODES) {
                    int pos = atomicAdd(&g_cur[d], 1);
                    g_bucket[pos] = s;
                }
            }
        }
    }
}

// ---------------------------------------------------------------------------
// K5: out[d] = relu( sum_{s in nbrs(d)} xf[s] + bias ). Warp per node.
// Re-zeroes g_cnt for the next replay.
// ---------------------------------------------------------------------------
__global__ void gather_bias_relu_kernel(const float* __restrict__ bias,
                                        float* __restrict__ out) {
    int gtid = blockIdx.x * blockDim.x + threadIdx.x;
    if (gtid < N_NODES) g_cnt[gtid] = 0;

    int node = gtid >> 5;
    int lane = threadIdx.x & 31;
    if (node >= N_NODES) return;

    int beg = g_off[node];
    int end = g_off[node + 1];

    float4 acc = reinterpret_cast<const float4*>(bias)[lane];
    const float4* xf4 = reinterpret_cast<const float4*>(g_xf);

    int i = beg;
    for (; i + 4 <= end; i += 4) {
        int s0 = g_bucket[i + 0];
        int s1 = g_bucket[i + 1];
        int s2 = g_bucket[i + 2];
        int s3 = g_bucket[i + 3];
        float4 v0 = xf4[(size_t)s0 * 32 + lane];
        float4 v1 = xf4[(size_t)s1 * 32 + lane];
        float4 v2 = xf4[(size_t)s2 * 32 + lane];
        float4 v3 = xf4[(size_t)s3 * 32 + lane];
        acc.x += (v0.x + v1.x) + (v2.x + v3.x);
        acc.y += (v0.y + v1.y) + (v2.y + v3.y);
        acc.z += (v0.z + v1.z) + (v2.z + v3.z);
        acc.w += (v0.w + v1.w) + (v2.w + v3.w);
    }
    for (; i < end; i++) {
        int s = g_bucket[i];
        float4 v = xf4[(size_t)s * 32 + lane];
        acc.x += v.x; acc.y += v.y; acc.z += v.z; acc.w += v.w;
    }

    float4 r;
    r.x = fmaxf(acc.x, 0.f);
    r.y = fmaxf(acc.y, 0.f);
    r.z = fmaxf(acc.z, 0.f);
    r.w = fmaxf(acc.w, 0.f);
    reinterpret_cast<float4*>(out)[(size_t)node * 32 + lane] = r;
}

// ---------------------------------------------------------------------------
extern "C" void kernel_launch(void* const* d_in, const int* in_sizes, int n_in,
                              void* d_out, int out_size) {
    const float* feat = (const float*)d_in[0];   // [50000,128] f32
    const int*   src  = (const int*)d_in[1];     // [800000] i32
    const int*   dst  = (const int*)d_in[2];     // [800000] i32
    const float* W    = (const float*)d_in[3];   // [128,128] f32
    const float* bias = (const float*)d_in[4];   // [128] f32
    float*       out  = (float*)d_out;           // [50000,128] f32

    (void)in_sizes; (void)n_in; (void)out_size;

    cudaFuncSetAttribute(fill_gemm_kernel,
                         cudaFuncAttributeMaxDynamicSharedMemorySize, SMEM_TOTAL);

    hist_kernel<<<HIST_BLOCKS + WPREP_BLOCKS, 256>>>(dst, W);
    scan_local_kernel<<<SCAN_GRID, SCAN_BLK>>>();
    scan_add_kernel<<<SCAN_GRID, SCAN_BLK>>>();
    fill_gemm_kernel<<<GEMM_BLOCKS + EDGE_BLOCKS, 512, SMEM_TOTAL>>>(src, dst, feat);

    {
        long long threads = (long long)N_NODES * 32;
        int blocks = (int)((threads + 255) / 256);
        gather_bias_relu_kernel<<<blocks, 256>>>(bias, out);
    }
}

// round 13
// speedup vs baseline: 1.3887x; 1.0273x over previous
#include <cuda_runtime.h>
#include <cuda_bf16.h>
#include <cstdint>

#define N_NODES 50000
#define N_EDGES 800000
#define FEATS   128
#define TILE_M  256
#define SCAN_BLK 1024
#define SCAN_GRID ((N_NODES + SCAN_BLK - 1) / SCAN_BLK)   // 49

#define GEMM_BLOCKS ((N_NODES + TILE_M - 1) / TILE_M)     // 196
#define HIST_BLK_EDGES 1024
#define HIST_BLOCKS ((N_EDGES + HIST_BLK_EDGES - 1) / HIST_BLK_EDGES) // 782
#define EDGE_BLK_EDGES 2048                               // 512 thr * 4 edges
#define EDGE_BLOCKS ((N_EDGES + EDGE_BLK_EDGES - 1) / EDGE_BLK_EDGES) // 391
#define WPREP_BLOCKS 8

// smem: swizzled 256-B-row bf16 tiles (no padding).
// off(r, c16) = r*256 + ((c16 ^ (r&7))<<4)  -> ldmatrix conflict-free.
#define SOFF_AHI  0
#define SOFF_ALO  65536
#define SOFF_WHI  131072
#define SOFF_WLO  163840
#define SMEM_TOTAL 196608   // 192 KB

// ---------------- device scratch (alloc-free rule: __device__ globals) -----
__device__ float g_xf[(size_t)N_NODES * FEATS];   // feat @ W^T
__device__ int   g_cnt[N_NODES];                  // per-dst degree (re-zeroed by gather)
__device__ int   g_off[N_NODES + 1];              // CSR offsets
__device__ int   g_cur[N_NODES];                  // fill cursors
__device__ int   g_bucket[N_EDGES];               // src ids bucketed by dst
__device__ int   g_part[SCAN_GRID];               // per-block totals
__device__ uint4 g_whi[FEATS * 16];               // W hi bf16, [128][128] packed
__device__ uint4 g_wlo[FEATS * 16];               // W lo bf16

// ============================ helpers ======================================
__device__ __forceinline__ uint32_t smem_u32(const void* p) {
    uint32_t a;
    asm("{ .reg .u64 t; cvta.to.shared.u64 t, %1; cvt.u32.u64 %0, t; }"
        : "=r"(a) : "l"(p));
    return a;
}
__device__ __forceinline__ uint32_t cvt_bf16x2(float hi, float lo) {
    uint32_t r;
    asm("cvt.rn.bf16x2.f32 %0, %1, %2;" : "=r"(r) : "f"(hi), "f"(lo));
    return r;
}
__device__ __forceinline__ void split8(const float4 u, const float4 v,
                                       uint4& hi, uint4& lo) {
    hi.x = cvt_bf16x2(u.y, u.x);
    hi.y = cvt_bf16x2(u.w, u.z);
    hi.z = cvt_bf16x2(v.y, v.x);
    hi.w = cvt_bf16x2(v.w, v.z);
    float h0 = __uint_as_float(hi.x << 16), h1 = __uint_as_float(hi.x & 0xFFFF0000u);
    float h2 = __uint_as_float(hi.y << 16), h3 = __uint_as_float(hi.y & 0xFFFF0000u);
    float h4 = __uint_as_float(hi.z << 16), h5 = __uint_as_float(hi.z & 0xFFFF0000u);
    float h6 = __uint_as_float(hi.w << 16), h7 = __uint_as_float(hi.w & 0xFFFF0000u);
    lo.x = cvt_bf16x2(u.y - h1, u.x - h0);
    lo.y = cvt_bf16x2(u.w - h3, u.z - h2);
    lo.z = cvt_bf16x2(v.y - h5, v.x - h4);
    lo.w = cvt_bf16x2(v.w - h7, v.z - h6);
}
// swizzled byte offset within a 256-B-row tile
__device__ __forceinline__ uint32_t swz(int r, int c16) {
    return (uint32_t)(r * 256) + (uint32_t)((c16 ^ (r & 7)) << 4);
}
#define LDSM_X4(r0, r1, r2, r3, addr)                                         \
    asm volatile("ldmatrix.sync.aligned.m8n8.x4.shared.b16 {%0,%1,%2,%3}, [%4];" \
                 : "=r"(r0), "=r"(r1), "=r"(r2), "=r"(r3) : "r"(addr))
#define MMA_BF16(d, a, b0, b1)                                                \
    asm volatile("mma.sync.aligned.m16n8k16.row.col.f32.bf16.bf16.f32 "       \
                 "{%0,%1,%2,%3}, {%4,%5,%6,%7}, {%8,%9}, {%0,%1,%2,%3};"      \
                 : "+f"(d[0]), "+f"(d[1]), "+f"(d[2]), "+f"(d[3])             \
                 : "r"(a[0]), "r"(a[1]), "r"(a[2]), "r"(a[3]), "r"(b0), "r"(b1))

// ---------------------------------------------------------------------------
// K1: histogram of dst (256 thr) + W hi/lo split (8 extra blocks).
// ---------------------------------------------------------------------------
__global__ void hist_kernel(const int* __restrict__ dst,
                            const float* __restrict__ W) {
    if (blockIdx.x < HIST_BLOCKS) {
        int e0 = blockIdx.x * HIST_BLK_EDGES + threadIdx.x * 4;
        if (e0 + 3 < N_EDGES) {
            int4 d4 = *reinterpret_cast<const int4*>(dst + e0);
            if ((unsigned)d4.x < N_NODES) atomicAdd(&g_cnt[d4.x], 1);
            if ((unsigned)d4.y < N_NODES) atomicAdd(&g_cnt[d4.y], 1);
            if ((unsigned)d4.z < N_NODES) atomicAdd(&g_cnt[d4.z], 1);
            if ((unsigned)d4.w < N_NODES) atomicAdd(&g_cnt[d4.w], 1);
        } else {
            for (int e = e0; e < N_EDGES; e++) {
                int d = dst[e];
                if ((unsigned)d < N_NODES) atomicAdd(&g_cnt[d], 1);
            }
        }
    } else {
        int g = (blockIdx.x - HIST_BLOCKS) * 256 + threadIdx.x;  // 0..2047
        int row = g >> 4, ch = g & 15;
        const float4* W4 = reinterpret_cast<const float4*>(W);
        float4 u = W4[row * 32 + ch * 2];
        float4 v = W4[row * 32 + ch * 2 + 1];
        uint4 hi, lo;
        split8(u, v, hi, lo);
        g_whi[row * 16 + ch] = hi;
        g_wlo[row * 16 + ch] = lo;
    }
}

// ---------------------------------------------------------------------------
// K2: per-block exclusive scan of g_cnt -> g_off; totals -> g_part.
// ---------------------------------------------------------------------------
__global__ void scan_local_kernel() {
    __shared__ int wsum[32];
    int tid  = threadIdx.x;
    int lane = tid & 31;
    int wid  = tid >> 5;
    int idx  = blockIdx.x * SCAN_BLK + tid;

    int x = (idx < N_NODES) ? g_cnt[idx] : 0;

    int v = x;
    #pragma unroll
    for (int d = 1; d < 32; d <<= 1) {
        int t = __shfl_up_sync(0xffffffff, v, d);
        if (lane >= d) v += t;
    }
    if (lane == 31) wsum[wid] = v;
    __syncthreads();
    if (wid == 0) {
        int w = wsum[lane];
        #pragma unroll
        for (int d = 1; d < 32; d <<= 1) {
            int t = __shfl_up_sync(0xffffffff, w, d);
            if (lane >= d) w += t;
        }
        wsum[lane] = w;
    }
    __syncthreads();

    int excl = v - x + ((wid > 0) ? wsum[wid - 1] : 0);
    if (idx < N_NODES) g_off[idx] = excl;
    if (tid == SCAN_BLK - 1) g_part[blockIdx.x] = excl + x;
}

// ---------------------------------------------------------------------------
// K3: add block offsets; copy to cursors; sentinel.
// ---------------------------------------------------------------------------
__global__ void scan_add_kernel() {
    __shared__ int s_off;
    int tid = threadIdx.x;
    if (tid < 32) {
        int v = 0;
        for (int j = tid; j < blockIdx.x; j += 32) v += g_part[j];
        #pragma unroll
        for (int d = 16; d > 0; d >>= 1) v += __shfl_down_sync(0xffffffff, v, d);
        if (tid == 0) s_off = v;
    }
    __syncthreads();

    int idx = blockIdx.x * SCAN_BLK + tid;
    if (idx < N_NODES) {
        int o = g_off[idx] + s_off;
        g_off[idx] = o;
        g_cur[idx] = o;
    }
    if (blockIdx.x == 0 && tid == 0) g_off[N_NODES] = N_EDGES;
}

// ---------------------------------------------------------------------------
// K4: FUSED fill + HMMA GEMM, 512 threads.
//   blocks [0, GEMM_BLOCKS)            : xf = feat @ W^T, 256-row tiles
//   blocks [GEMM_BLOCKS, +EDGE_BLOCKS) : bucket fill (2048 edges/block)
// GEMM: 16 warps = 8 mt-pairs x 2 col-halves. Each warp computes TWO m-tiles
// (32 rows) reusing the same W fragments -> W crossbar traffic per row halved.
// Chains: Ahi*Whi + Ahi*Wlo + Alo*Whi, fp32 acc.
// ---------------------------------------------------------------------------
__global__ void __launch_bounds__(512)
fill_gemm_kernel(const int* __restrict__ src,
                 const int* __restrict__ dst,
                 const float* __restrict__ A)   // feat [N,128]
{
    if (blockIdx.x < GEMM_BLOCKS) {
        // ---------------- GEMM role ----------------
        extern __shared__ char smc[];
        const uint32_t sb = smem_u32(smc);
        const int tid  = threadIdx.x;
        const int lane = tid & 31;
        const int wid  = tid >> 5;              // 0..15
        const int row0 = blockIdx.x * TILE_M;

        // ---- stage A hi/lo: 256 rows x 16 chunks of 8 floats (swizzled) ----
        {
            const float4* A4 = reinterpret_cast<const float4*>(A);
            #pragma unroll
            for (int t = 0; t < 8; t++) {
                int i = tid + t * 512;          // 0..4095
                int r = i >> 4, g = i & 15;
                int row = row0 + r;
                float4 u, v;
                if (row < N_NODES) {
                    u = A4[(size_t)row * 32 + g * 2];
                    v = A4[(size_t)row * 32 + g * 2 + 1];
                } else {
                    u = make_float4(0.f, 0.f, 0.f, 0.f);
                    v = u;
                }
                uint4 hi, lo;
                split8(u, v, hi, lo);
                uint32_t off = swz(r, g);
                *reinterpret_cast<uint4*>(smc + SOFF_AHI + off) = hi;
                *reinterpret_cast<uint4*>(smc + SOFF_ALO + off) = lo;
            }
        }
        // ---- stage W hi/lo from pre-split globals (swizzled) ----
        {
            #pragma unroll
            for (int t = 0; t < 4; t++) {
                int i = tid + t * 512;          // 0..2047
                int r = i >> 4, g = i & 15;
                uint32_t off = swz(r, g);
                *reinterpret_cast<uint4*>(smc + SOFF_WHI + off) = g_whi[i];
                *reinterpret_cast<uint4*>(smc + SOFF_WLO + off) = g_wlo[i];
            }
        }
        __syncthreads();

        const int mt2 = wid & 7;                // covers rows mt2*32 .. +31
        const int ch  = wid >> 3;               // col half (64 cols)

        // A ldmatrix lane geometry (two m-tiles A and B)
        const int lrow  = lane & 15;
        const int khalf = lane >> 4;            // 0/1 -> k-offset 0/8 (c16 +0/+1)
        const int rA = mt2 * 32 + lrow;
        const int rB = rA + 16;
        const uint32_t rAbase = (uint32_t)(rA * 256), rAm = (uint32_t)(rA & 7);
        const uint32_t rBbase = (uint32_t)(rB * 256), rBm = (uint32_t)(rB & 7);

        // W ldmatrix lane geometry
        const int lr = lane & 7, q = lane >> 3;
        const int wrow_lane = lr + ((q >> 1) << 3);   // 0..15 within n-tile pair
        const int wk = q & 1;                          // c16 offset

        float accA[8][4], accB[8][4];
        #pragma unroll
        for (int nt = 0; nt < 8; nt++)
            #pragma unroll
            for (int c = 0; c < 4; c++) { accA[nt][c] = 0.f; accB[nt][c] = 0.f; }

        #pragma unroll
        for (int ks = 0; ks < 8; ks++) {
            const int c16a = ks * 2 + khalf;
            uint32_t aAoff = rAbase + (((uint32_t)c16a ^ rAm) << 4);
            uint32_t aBoff = rBbase + (((uint32_t)c16a ^ rBm) << 4);
            uint32_t ahiA[4], aloA[4], ahiB[4], aloB[4];
            LDSM_X4(ahiA[0], ahiA[1], ahiA[2], ahiA[3], sb + SOFF_AHI + aAoff);
            LDSM_X4(aloA[0], aloA[1], aloA[2], aloA[3], sb + SOFF_ALO + aAoff);
            LDSM_X4(ahiB[0], ahiB[1], ahiB[2], ahiB[3], sb + SOFF_AHI + aBoff);
            LDSM_X4(aloB[0], aloB[1], aloB[2], aloB[3], sb + SOFF_ALO + aBoff);

            #pragma unroll
            for (int np = 0; np < 4; np++) {
                int wrow = ch * 64 + np * 16 + wrow_lane;
                int c16w = ks * 2 + wk;
                uint32_t woff = (uint32_t)(wrow * 256)
                              + (((uint32_t)c16w ^ (uint32_t)(wrow & 7)) << 4);
                uint32_t bh[4], bl[4];
                LDSM_X4(bh[0], bh[1], bh[2], bh[3], sb + SOFF_WHI + woff);
                LDSM_X4(bl[0], bl[1], bl[2], bl[3], sb + SOFF_WLO + woff);

                MMA_BF16(accA[2 * np],     ahiA, bh[0], bh[1]);
                MMA_BF16(accA[2 * np],     ahiA, bl[0], bl[1]);
                MMA_BF16(accA[2 * np],     aloA, bh[0], bh[1]);
                MMA_BF16(accA[2 * np + 1], ahiA, bh[2], bh[3]);
                MMA_BF16(accA[2 * np + 1], ahiA, bl[2], bl[3]);
                MMA_BF16(accA[2 * np + 1], aloA, bh[2], bh[3]);

                MMA_BF16(accB[2 * np],     ahiB, bh[0], bh[1]);
                MMA_BF16(accB[2 * np],     ahiB, bl[0], bl[1]);
                MMA_BF16(accB[2 * np],     aloB, bh[0], bh[1]);
                MMA_BF16(accB[2 * np + 1], ahiB, bh[2], bh[3]);
                MMA_BF16(accB[2 * np + 1], ahiB, bl[2], bl[3]);
                MMA_BF16(accB[2 * np + 1], aloB, bh[2], bh[3]);
            }
        }

        // ---- epilogue (both m-tiles) ----
        {
            int c0 = ch * 64 + 2 * (lane & 3);
            int rA0 = row0 + mt2 * 32 + (lane >> 2);
            int rB0 = rA0 + 16;
            #pragma unroll
            for (int nt = 0; nt < 8; nt++) {
                int col = c0 + nt * 8;
                if (rA0 < N_NODES)
                    *reinterpret_cast<float2*>(&g_xf[(size_t)rA0 * FEATS + col]) =
                        make_float2(accA[nt][0], accA[nt][1]);
                if (rA0 + 8 < N_NODES)
                    *reinterpret_cast<float2*>(&g_xf[(size_t)(rA0 + 8) * FEATS + col]) =
                        make_float2(accA[nt][2], accA[nt][3]);
                if (rB0 < N_NODES)
                    *reinterpret_cast<float2*>(&g_xf[(size_t)rB0 * FEATS + col]) =
                        make_float2(accB[nt][0], accB[nt][1]);
                if (rB0 + 8 < N_NODES)
                    *reinterpret_cast<float2*>(&g_xf[(size_t)(rB0 + 8) * FEATS + col]) =
                        make_float2(accB[nt][2], accB[nt][3]);
            }
        }
    } else {
        // ---------------- fill role ----------------
        int b = blockIdx.x - GEMM_BLOCKS;
        int e0 = b * EDGE_BLK_EDGES + threadIdx.x * 4;
        if (e0 + 3 < N_EDGES) {
            int4 s4 = *reinterpret_cast<const int4*>(src + e0);
            int4 d4 = *reinterpret_cast<const int4*>(dst + e0);
            int p0 = ((unsigned)d4.x < N_NODES) ? atomicAdd(&g_cur[d4.x], 1) : -1;
            int p1 = ((unsigned)d4.y < N_NODES) ? atomicAdd(&g_cur[d4.y], 1) : -1;
            int p2 = ((unsigned)d4.z < N_NODES) ? atomicAdd(&g_cur[d4.z], 1) : -1;
            int p3 = ((unsigned)d4.w < N_NODES) ? atomicAdd(&g_cur[d4.w], 1) : -1;
            if (p0 >= 0 && (unsigned)s4.x < N_NODES) g_bucket[p0] = s4.x;
            if (p1 >= 0 && (unsigned)s4.y < N_NODES) g_bucket[p1] = s4.y;
            if (p2 >= 0 && (unsigned)s4.z < N_NODES) g_bucket[p2] = s4.z;
            if (p3 >= 0 && (unsigned)s4.w < N_NODES) g_bucket[p3] = s4.w;
        } else {
            for (int e = e0; e < N_EDGES; e++) {
                int d = dst[e];
                int s = src[e];
                if ((unsigned)d < N_NODES && (unsigned)s < N_NODES) {
                    int pos = atomicAdd(&g_cur[d], 1);
                    g_bucket[pos] = s;
                }
            }
        }
    }
}

// ---------------------------------------------------------------------------
// K5: out[d] = relu( sum_{s in nbrs(d)} xf[s] + bias ). Warp per node.
// Re-zeroes g_cnt for the next replay.
// ---------------------------------------------------------------------------
__global__ void gather_bias_relu_kernel(const float* __restrict__ bias,
                                        float* __restrict__ out) {
    int gtid = blockIdx.x * blockDim.x + threadIdx.x;
    if (gtid < N_NODES) g_cnt[gtid] = 0;

    int node = gtid >> 5;
    int lane = threadIdx.x & 31;
    if (node >= N_NODES) return;

    int beg = g_off[node];
    int end = g_off[node + 1];

    float4 acc = reinterpret_cast<const float4*>(bias)[lane];
    const float4* xf4 = reinterpret_cast<const float4*>(g_xf);

    int i = beg;
    for (; i + 4 <= end; i += 4) {
        int s0 = g_bucket[i + 0];
        int s1 = g_bucket[i + 1];
        int s2 = g_bucket[i + 2];
        int s3 = g_bucket[i + 3];
        float4 v0 = xf4[(size_t)s0 * 32 + lane];
        float4 v1 = xf4[(size_t)s1 * 32 + lane];
        float4 v2 = xf4[(size_t)s2 * 32 + lane];
        float4 v3 = xf4[(size_t)s3 * 32 + lane];
        acc.x += (v0.x + v1.x) + (v2.x + v3.x);
        acc.y += (v0.y + v1.y) + (v2.y + v3.y);
        acc.z += (v0.z + v1.z) + (v2.z + v3.z);
        acc.w += (v0.w + v1.w) + (v2.w + v3.w);
    }
    for (; i < end; i++) {
        int s = g_bucket[i];
        float4 v = xf4[(size_t)s * 32 + lane];
        acc.x += v.x; acc.y += v.y; acc.z += v.z; acc.w += v.w;
    }

    float4 r;
    r.x = fmaxf(acc.x, 0.f);
    r.y = fmaxf(acc.y, 0.f);
    r.z = fmaxf(acc.z, 0.f);
    r.w = fmaxf(acc.w, 0.f);
    reinterpret_cast<float4*>(out)[(size_t)node * 32 + lane] = r;
}

// ---------------------------------------------------------------------------
extern "C" void kernel_launch(void* const* d_in, const int* in_sizes, int n_in,
                              void* d_out, int out_size) {
    const float* feat = (const float*)d_in[0];   // [50000,128] f32
    const int*   src  = (const int*)d_in[1];     // [800000] i32
    const int*   dst  = (const int*)d_in[2];     // [800000] i32
    const float* W    = (const float*)d_in[3];   // [128,128] f32
    const float* bias = (const float*)d_in[4];   // [128] f32
    float*       out  = (float*)d_out;           // [50000,128] f32

    (void)in_sizes; (void)n_in; (void)out_size;

    cudaFuncSetAttribute(fill_gemm_kernel,
                         cudaFuncAttributeMaxDynamicSharedMemorySize, SMEM_TOTAL);

    hist_kernel<<<HIST_BLOCKS + WPREP_BLOCKS, 256>>>(dst, W);
    scan_local_kernel<<<SCAN_GRID, SCAN_BLK>>>();
    scan_add_kernel<<<SCAN_GRID, SCAN_BLK>>>();
    fill_gemm_kernel<<<GEMM_BLOCKS + EDGE_BLOCKS, 512, SMEM_TOTAL>>>(src, dst, feat);

    {
        long long threads = (long long)N_NODES * 32;
        int blocks = (int)((threads + 255) / 256);
        gather_bias_relu_kernel<<<blocks, 256>>>(bias, out);
    }
}